// round 1
// baseline (speedup 1.0000x reference)
#include <cuda_runtime.h>
#include <math.h>

#define D 128
#define MAXN 100000
#define MAXE 1600000

// ---------------- device scratch (no allocation allowed) ----------------
__device__ float g_t[MAXN * D];
__device__ float g_q[MAXN * D];
__device__ float g_k[MAXN * D];
__device__ float g_v[MAXN * D];
__device__ float g_x[MAXN * D];
__device__ int   g_cnt[MAXN];
__device__ int   g_off[MAXN + 1];
__device__ int   g_cur[MAXN];
__device__ int   g_esrc[MAXE];

// ---------------- CSR build ----------------
__global__ void zero_cnt_kernel(int N) {
    int i = blockIdx.x * blockDim.x + threadIdx.x;
    if (i < N) g_cnt[i] = 0;
}

__global__ void hist_kernel(const int* __restrict__ dst, int E) {
    int i = blockIdx.x * blockDim.x + threadIdx.x;
    if (i < E) atomicAdd(&g_cnt[dst[i]], 1);
}

// single-block scan over N counts -> exclusive offsets (+ cursor copy)
__global__ void scan_kernel(int N, int E) {
    __shared__ int sh[1024];
    int t = threadIdx.x;
    int per = (N + 1023) >> 10;
    int b = t * per;
    int e = min(b + per, N);
    int s = 0;
    for (int i = b; i < e; i++) s += g_cnt[i];
    sh[t] = s;
    __syncthreads();
    for (int o = 1; o < 1024; o <<= 1) {
        int v = 0;
        if (t >= o) v = sh[t - o];
        __syncthreads();
        sh[t] += v;
        __syncthreads();
    }
    int run = sh[t] - s;  // exclusive prefix for this thread's chunk
    for (int i = b; i < e; i++) {
        g_off[i] = run;
        g_cur[i] = run;
        run += g_cnt[i];
    }
    if (t == 0) g_off[N] = E;
}

__global__ void scatter_kernel(const int* __restrict__ src,
                               const int* __restrict__ dst, int E) {
    int i = blockIdx.x * blockDim.x + threadIdx.x;
    if (i < E) {
        int dn = dst[i];
        int p = atomicAdd(&g_cur[dn], 1);
        g_esrc[p] = src[i];   // store gather index directly (skip edge-id indirection)
    }
}

// ---------------- log_map at origin: t = (2/sc)*atanh(sc*||x||)*x/||x|| ----------------
__global__ void log_kernel(const float* __restrict__ x,
                           const float* __restrict__ curv, int N) {
    int lane = threadIdx.x & 31;
    int node = blockIdx.x * (blockDim.x >> 5) + (threadIdx.x >> 5);
    if (node >= N) return;
    float4 xv = ((const float4*)x)[node * 32 + lane];
    float n2 = xv.x * xv.x + xv.y * xv.y + xv.z * xv.z + xv.w * xv.w;
    #pragma unroll
    for (int o = 16; o; o >>= 1) n2 += __shfl_xor_sync(0xffffffffu, n2, o);
    float nrm = sqrtf(n2);
    float sc = sqrtf(curv[0]);
    float f = (nrm > 1e-30f) ? (2.0f / sc) * atanhf(sc * nrm) / nrm : 2.0f;
    float4 tv = make_float4(f * xv.x, f * xv.y, f * xv.z, f * xv.w);
    ((float4*)g_t)[node * 32 + lane] = tv;
}

// ---------------- fused q/k/v GEMM: out = t @ W^T + b ----------------
// Persistent blocks. All 3 W held transposed+swizzled in SMEM (192KB),
// A tile (64 rows x 128) streamed per tile. 256 thr, 8x4 micro tiles.
__global__ void __launch_bounds__(256, 1)
qkv_gemm(const float* __restrict__ Wq, const float* __restrict__ bq,
         const float* __restrict__ Wk, const float* __restrict__ bk,
         const float* __restrict__ Wv, const float* __restrict__ bv,
         int N, int numTiles) {
    extern __shared__ float sm[];
    float* sW = sm;              // 3 * 128*128
    float* sA = sm + 3 * 16384;  // 64 * 128

    int tid = threadIdx.x;
    int tx = tid & 31;
    int ty = tid >> 5;           // 0..7

    const float* Ws[3] = {Wq, Wk, Wv};
    const float* Bs[3] = {bq, bk, bv};

    // Load W^T into SMEM with XOR-32 swizzle: element W[c][k] stored at
    // sW[w] + k*128 + ((c&96) | ((c&31)^(k&31)))
    for (int w = 0; w < 3; w++) {
        const float4* srcp = (const float4*)Ws[w];
        float* dstp = sW + w * 16384;
        for (int idx = tid; idx < 4096; idx += 256) {
            int c = idx >> 5, k4 = idx & 31;
            float4 val = srcp[c * 32 + k4];
            int chi = c & 96, clo = c & 31;
            int k = k4 * 4;
            dstp[(k + 0) * 128 + (chi | (clo ^ ((k + 0) & 31)))] = val.x;
            dstp[(k + 1) * 128 + (chi | (clo ^ ((k + 1) & 31)))] = val.y;
            dstp[(k + 2) * 128 + (chi | (clo ^ ((k + 2) & 31)))] = val.z;
            dstp[(k + 3) * 128 + (chi | (clo ^ ((k + 3) & 31)))] = val.w;
        }
    }
    // bias values for this thread's 4 columns, per weight
    float bb[3][4];
    #pragma unroll
    for (int w = 0; w < 3; w++)
        #pragma unroll
        for (int j = 0; j < 4; j++) bb[w][j] = Bs[w][tx + 32 * j];
    __syncthreads();

    int r0 = ty * 8;
    for (int tile = blockIdx.x; tile < numTiles; tile += gridDim.x) {
        int row0 = tile * 64;
        // load A tile (zero-fill past N)
        for (int idx = tid; idx < 2048; idx += 256) {
            int r = idx >> 5, k4 = idx & 31;
            int row = row0 + r;
            float4 val = (row < N) ? ((const float4*)g_t)[row * 32 + k4]
                                   : make_float4(0.f, 0.f, 0.f, 0.f);
            ((float4*)sA)[idx] = val;
        }
        __syncthreads();

        for (int w = 0; w < 3; w++) {
            const float* Wt = sW + w * 16384;
            float acc[8][4];
            #pragma unroll
            for (int i = 0; i < 8; i++)
                #pragma unroll
                for (int j = 0; j < 4; j++) acc[i][j] = 0.f;

            for (int k = 0; k < 128; k += 4) {
                float4 a4[8];
                #pragma unroll
                for (int i = 0; i < 8; i++)
                    a4[i] = *(const float4*)(sA + (r0 + i) * 128 + k);
                #pragma unroll
                for (int u = 0; u < 4; u++) {
                    int kk = k + u;
                    int txk = tx ^ (kk & 31);
                    const float* wrow = Wt + kk * 128 + txk;
                    float b0 = wrow[0];
                    float b1 = wrow[32];
                    float b2 = wrow[64];
                    float b3 = wrow[96];
                    #pragma unroll
                    for (int i = 0; i < 8; i++) {
                        float av = (u == 0) ? a4[i].x : (u == 1) ? a4[i].y
                                 : (u == 2) ? a4[i].z : a4[i].w;
                        acc[i][0] = fmaf(av, b0, acc[i][0]);
                        acc[i][1] = fmaf(av, b1, acc[i][1]);
                        acc[i][2] = fmaf(av, b2, acc[i][2]);
                        acc[i][3] = fmaf(av, b3, acc[i][3]);
                    }
                }
            }
            float* outp = (w == 0) ? g_q : (w == 1) ? g_k : g_v;
            #pragma unroll
            for (int i = 0; i < 8; i++) {
                int row = row0 + r0 + i;
                if (row < N) {
                    float* op = outp + row * 128 + tx;
                    op[0]  = acc[i][0] + bb[w][0];
                    op[32] = acc[i][1] + bb[w][1];
                    op[64] = acc[i][2] + bb[w][2];
                    op[96] = acc[i][3] + bb[w][3];
                }
            }
        }
        __syncthreads();
    }
}

// ---------------- fused attention (online softmax) + exp_map ----------------
__global__ void __launch_bounds__(256)
edge_kernel(const float* __restrict__ curv, float* __restrict__ out, int N) {
    int lane = threadIdx.x & 31;
    int node = blockIdx.x * 8 + (threadIdx.x >> 5);
    if (node >= N) return;

    float4 qr = ((const float4*)g_q)[node * 32 + lane];
    int e0 = g_off[node];
    int e1 = g_off[node + 1];

    float m = -3.0e38f;
    float z = 0.f;
    float4 acc = make_float4(0.f, 0.f, 0.f, 0.f);

    for (int e = e0; e < e1; e++) {
        int s = g_esrc[e];
        float4 kr = ((const float4*)g_k)[s * 32 + lane];
        float4 vr = ((const float4*)g_v)[s * 32 + lane];
        float d = qr.x * kr.x + qr.y * kr.y + qr.z * kr.z + qr.w * kr.w;
        #pragma unroll
        for (int o = 16; o; o >>= 1) d += __shfl_xor_sync(0xffffffffu, d, o);
        float ev = d * 0.08838834764831845f;  // 1/sqrt(128)
        float mn = fmaxf(m, ev);
        float so = expf(m - mn);
        float p = expf(ev - mn);
        z = z * so + p;
        acc.x = acc.x * so + p * vr.x;
        acc.y = acc.y * so + p * vr.y;
        acc.z = acc.z * so + p * vr.z;
        acc.w = acc.w * so + p * vr.w;
        m = mn;
    }
    float inv = 1.0f / z;
    float4 h = make_float4(acc.x * inv, acc.y * inv, acc.z * inv, acc.w * inv);

    // exp_map at origin: tanh(sc*||h||/2) * h / (sc*||h||)
    float n2 = h.x * h.x + h.y * h.y + h.z * h.z + h.w * h.w;
    #pragma unroll
    for (int o = 16; o; o >>= 1) n2 += __shfl_xor_sync(0xffffffffu, n2, o);
    float nrm = sqrtf(n2);
    float sc = sqrtf(curv[0]);
    float f = (nrm > 1e-30f) ? tanhf(0.5f * sc * nrm) / (sc * nrm) : 0.5f;
    ((float4*)out)[node * 32 + lane] =
        make_float4(f * h.x, f * h.y, f * h.z, f * h.w);
}

// ---------------- launch ----------------
extern "C" void kernel_launch(void* const* d_in, const int* in_sizes, int n_in,
                              void* d_out, int out_size) {
    const float* emb  = (const float*)d_in[0];
    const float* Wq   = (const float*)d_in[1];
    const float* bq   = (const float*)d_in[2];
    const float* Wk   = (const float*)d_in[3];
    const float* bk   = (const float*)d_in[4];
    const float* Wv   = (const float*)d_in[5];
    const float* bv   = (const float*)d_in[6];
    const float* curv = (const float*)d_in[7];
    const int*   src  = (const int*)d_in[8];
    const int*   dst  = (const int*)d_in[9];

    int N = in_sizes[0] / D;
    int E = in_sizes[8];
    int L = in_sizes[1] / (D * D);

    cudaFuncSetAttribute(qkv_gemm, cudaFuncAttributeMaxDynamicSharedMemorySize,
                         229376);

    void* gx_v = nullptr;
    cudaGetSymbolAddress(&gx_v, g_x);
    float* gx = (float*)gx_v;

    // CSR build (per launch; deterministic work)
    zero_cnt_kernel<<<(N + 255) / 256, 256>>>(N);
    hist_kernel<<<(E + 255) / 256, 256>>>(dst, E);
    scan_kernel<<<1, 1024>>>(N, E);
    scatter_kernel<<<(E + 255) / 256, 256>>>(src, dst, E);

    int numTiles = (N + 63) / 64;
    int nodeBlocks = (N + 7) / 8;

    for (int l = 0; l < L; l++) {
        const float* xin = (l == 0) ? emb : gx;
        float* xout = (l == L - 1) ? (float*)d_out : gx;
        log_kernel<<<nodeBlocks, 256>>>(xin, curv, N);
        qkv_gemm<<<148, 256, 229376>>>(Wq + l * D * D, bq + l * D,
                                       Wk + l * D * D, bk + l * D,
                                       Wv + l * D * D, bv + l * D,
                                       N, numTiles);
        edge_kernel<<<nodeBlocks, 256>>>(curv, xout, N);
    }
}

// round 4
// speedup vs baseline: 2.5638x; 2.5638x over previous
#include <cuda_runtime.h>
#include <cuda_bf16.h>
#include <math.h>
#include <stdint.h>

#define D 128
#define MAXN 100000
#define MAXE 1600000

// ---------------- device scratch ----------------
__device__ float g_q[MAXN * D];
__device__ float g_k[MAXN * D];
__device__ float g_v[MAXN * D];
__device__ float g_x[MAXN * D];
__device__ int   g_cnt[MAXN];
__device__ int   g_off[MAXN + 1];
__device__ int   g_cur[MAXN];
__device__ int   g_esrc[MAXE];
__device__ int   g_bsum[128];
__device__ int   g_btop[128];

// ---------------- helpers ----------------
__device__ __forceinline__ uint32_t smem_u32(const void* p) {
    uint32_t a;
    asm("{ .reg .u64 t; cvta.to.shared.u64 t, %1; cvt.u32.u64 %0, t; }"
        : "=r"(a) : "l"(p));
    return a;
}
__device__ __forceinline__ unsigned short bfh(float x) {
    return __bfloat16_as_ushort(__float2bfloat16_rn(x));
}
__device__ __forceinline__ float bff(float x) {
    return __bfloat162float(__float2bfloat16_rn(x));
}
__device__ __forceinline__ unsigned pk(float a, float b) {
    return (unsigned)bfh(a) | ((unsigned)bfh(b) << 16);
}
__device__ __forceinline__ float wredsum(float v) {
    #pragma unroll
    for (int o = 16; o; o >>= 1) v += __shfl_xor_sync(0xffffffffu, v, o);
    return v;
}
__device__ __forceinline__ void ldsm_x4(uint32_t* r, uint32_t addr) {
    asm volatile("ldmatrix.sync.aligned.m8n8.x4.shared.b16 {%0,%1,%2,%3}, [%4];"
                 : "=r"(r[0]), "=r"(r[1]), "=r"(r[2]), "=r"(r[3]) : "r"(addr));
}
__device__ __forceinline__ void mma16816(float* d, const uint32_t* a,
                                         uint32_t b0, uint32_t b1) {
    asm volatile(
        "mma.sync.aligned.m16n8k16.row.col.f32.bf16.bf16.f32 "
        "{%0,%1,%2,%3}, {%4,%5,%6,%7}, {%8,%9}, {%0,%1,%2,%3};"
        : "+f"(d[0]), "+f"(d[1]), "+f"(d[2]), "+f"(d[3])
        : "r"(a[0]), "r"(a[1]), "r"(a[2]), "r"(a[3]), "r"(b0), "r"(b1));
}

// ---------------- CSR build ----------------
__global__ void zero_cnt_kernel(int N) {
    int i = blockIdx.x * blockDim.x + threadIdx.x;
    if (i < N) g_cnt[i] = 0;
}
__global__ void hist_kernel(const int* __restrict__ dst, int E) {
    int i = blockIdx.x * blockDim.x + threadIdx.x;
    if (i < E) atomicAdd(&g_cnt[dst[i]], 1);
}
__global__ void scan_local(int N) {
    __shared__ int sh[256];
    int b = blockIdx.x, t = threadIdx.x;
    int i0 = b * 1024 + t * 4;
    int c0 = (i0 + 0 < N) ? g_cnt[i0 + 0] : 0;
    int c1 = (i0 + 1 < N) ? g_cnt[i0 + 1] : 0;
    int c2 = (i0 + 2 < N) ? g_cnt[i0 + 2] : 0;
    int c3 = (i0 + 3 < N) ? g_cnt[i0 + 3] : 0;
    int s = c0 + c1 + c2 + c3;
    sh[t] = s;
    __syncthreads();
    for (int o = 1; o < 256; o <<= 1) {
        int v = (t >= o) ? sh[t - o] : 0;
        __syncthreads();
        sh[t] += v;
        __syncthreads();
    }
    int ex = sh[t] - s;
    if (i0 + 0 < N) g_off[i0 + 0] = ex; ex += c0;
    if (i0 + 1 < N) g_off[i0 + 1] = ex; ex += c1;
    if (i0 + 2 < N) g_off[i0 + 2] = ex; ex += c2;
    if (i0 + 3 < N) g_off[i0 + 3] = ex;
    if (t == 255) g_bsum[b] = sh[255];
}
__global__ void scan_tops(int nb) {
    __shared__ int sh[128];
    int t = threadIdx.x;
    int v = (t < nb) ? g_bsum[t] : 0;
    sh[t] = v;
    __syncthreads();
    for (int o = 1; o < 128; o <<= 1) {
        int u = (t >= o) ? sh[t - o] : 0;
        __syncthreads();
        sh[t] += u;
        __syncthreads();
    }
    g_btop[t] = sh[t] - v;
}
__global__ void scan_add(int N, int E) {
    int i = blockIdx.x * blockDim.x + threadIdx.x;
    if (i < N) {
        int o = g_off[i] + g_btop[i >> 10];
        g_off[i] = o;
        g_cur[i] = o;
    }
    if (i == 0) g_off[N] = E;
}
__global__ void scatter_kernel(const int* __restrict__ src,
                               const int* __restrict__ dst, int E) {
    int i = blockIdx.x * blockDim.x + threadIdx.x;
    if (i < E) {
        int p = atomicAdd(&g_cur[dst[i]], 1);
        g_esrc[p] = src[i];
    }
}

// ---------------- fused log_map + q/k/v GEMM (HMMA mma.sync bf16) ----------------
// SMEM panels: 128 rows x 256 bytes, chunk-XOR swizzle: chunk' = chunk ^ (row&7)
#define AH_OFF   0
#define AL_OFF   32768
#define WQ_OFF   65536
#define WK_OFF   98304
#define WVH_OFF  131072
#define WVL_OFF  163840
#define BIAS_OFF 196608
#define GEMM_SMEM 199680

// one GEMM pass: acc += A(panel Ap) @ W(panel Bp)^T for this warp's 16 rows
__device__ __forceinline__ void gemm_pass(float (*acc)[4], uint32_t Ap,
                                          uint32_t Bp, int lane, int R0) {
    int arow = R0 + (lane & 15);
    int brl = lane & 15;
    int chi = lane >> 4;
    uint32_t abase = Ap + arow * 256;
    int asw = arow & 7;
    #pragma unroll
    for (int kk = 0; kk < 8; kk++) {
        int cidx = kk * 2 + chi;
        uint32_t a[4];
        ldsm_x4(a, abase + (uint32_t)((cidx ^ asw) << 4));
        #pragma unroll
        for (int nb2 = 0; nb2 < 8; nb2++) {
            int brow = nb2 * 16 + brl;
            uint32_t b[4];
            // NON-trans: panel rows are n, 16 contiguous k-bytes per lane —
            // this IS the col-major-B fragment for row.col mma.
            ldsm_x4(b, Bp + brow * 256 + (uint32_t)((cidx ^ (brow & 7)) << 4));
            mma16816(acc[nb2 * 2 + 0], a, b[0], b[2]);
            mma16816(acc[nb2 * 2 + 1], a, b[1], b[3]);
        }
    }
}

__device__ __forceinline__ void store_out(float (*acc)[4], float* out,
                                          const float* bias, int lane, int R0,
                                          int row0, int N) {
    int g = lane >> 2, t = lane & 3;
    int r0g = row0 + R0 + g;
    int r1g = r0g + 8;
    #pragma unroll
    for (int nb = 0; nb < 16; nb++) {
        int col = nb * 8 + 2 * t;
        float b0 = bias[col], b1 = bias[col + 1];
        if (r0g < N)
            *(float2*)(out + r0g * 128 + col) =
                make_float2(acc[nb][0] + b0, acc[nb][1] + b1);
        if (r1g < N)
            *(float2*)(out + r1g * 128 + col) =
                make_float2(acc[nb][2] + b0, acc[nb][3] + b1);
    }
}

__global__ void __launch_bounds__(256, 1)
qkv_gemm_hmma(const float* __restrict__ xin,
              const float* __restrict__ Wq, const float* __restrict__ bq,
              const float* __restrict__ Wk, const float* __restrict__ bk,
              const float* __restrict__ Wv, const float* __restrict__ bv,
              const float* __restrict__ curv, int N, int numTiles) {
    extern __shared__ char dsm[];
    char* SB = (char*)((((uintptr_t)dsm) + 1023) & ~(uintptr_t)1023);
    uint32_t sb = smem_u32(SB);
    float* sbias = (float*)(SB + BIAS_OFF);

    int tid = threadIdx.x;
    int lane = tid & 31;
    int wid = tid >> 5;

    // ---- weights -> SMEM (bf16 hi; lo only for Wv), swizzled ----
    for (int it = 0; it < 16; it++) {
        int c = wid * 16 + it;
        float4 wq = ((const float4*)Wq)[c * 32 + lane];
        float4 wk = ((const float4*)Wk)[c * 32 + lane];
        float4 wv = ((const float4*)Wv)[c * 32 + lane];
        uint32_t off = (uint32_t)(c * 256 + (((lane >> 1) ^ (c & 7)) << 4) +
                                  (lane & 1) * 8);
        *(uint2*)(SB + WQ_OFF + off) = make_uint2(pk(wq.x, wq.y), pk(wq.z, wq.w));
        *(uint2*)(SB + WK_OFF + off) = make_uint2(pk(wk.x, wk.y), pk(wk.z, wk.w));
        *(uint2*)(SB + WVH_OFF + off) = make_uint2(pk(wv.x, wv.y), pk(wv.z, wv.w));
        float lx = wv.x - bff(wv.x), ly = wv.y - bff(wv.y);
        float lz = wv.z - bff(wv.z), lw = wv.w - bff(wv.w);
        *(uint2*)(SB + WVL_OFF + off) = make_uint2(pk(lx, ly), pk(lz, lw));
    }
    if (tid < 128) {
        sbias[tid] = bq[tid];
        sbias[128 + tid] = bk[tid];
        sbias[256 + tid] = bv[tid];
    }
    __syncthreads();

    float sc = sqrtf(curv[0]);
    float inv_sc2 = 2.0f / sc;
    int R0 = wid * 16;

    for (int tile = blockIdx.x; tile < numTiles; tile += gridDim.x) {
        int row0 = tile * 128;
        // ---- A fill: log_map(x) -> bf16 hi/lo panels ----
        for (int it = 0; it < 16; it++) {
            int m = wid * 16 + it;
            int grow = row0 + m;
            float4 xv = (grow < N) ? ((const float4*)xin)[grow * 32 + lane]
                                   : make_float4(0.f, 0.f, 0.f, 0.f);
            float n2 = wredsum(xv.x * xv.x + xv.y * xv.y + xv.z * xv.z + xv.w * xv.w);
            float nrm = sqrtf(n2);
            float f = (nrm > 1e-30f) ? inv_sc2 * atanhf(sc * nrm) / nrm : 2.0f;
            float tx = f * xv.x, ty = f * xv.y, tz = f * xv.z, tw = f * xv.w;
            uint32_t off = (uint32_t)(m * 256 + (((lane >> 1) ^ (m & 7)) << 4) +
                                      (lane & 1) * 8);
            *(uint2*)(SB + AH_OFF + off) = make_uint2(pk(tx, ty), pk(tz, tw));
            float lx = tx - bff(tx), ly = ty - bff(ty);
            float lz = tz - bff(tz), lw = tw - bff(tw);
            *(uint2*)(SB + AL_OFF + off) = make_uint2(pk(lx, ly), pk(lz, lw));
        }
        __syncthreads();

        float acc[16][4];
        // ---- q = Ah @ Wq^T ----
        #pragma unroll
        for (int i = 0; i < 16; i++)
            #pragma unroll
            for (int j = 0; j < 4; j++) acc[i][j] = 0.f;
        gemm_pass(acc, sb + AH_OFF, sb + WQ_OFF, lane, R0);
        store_out(acc, g_q, sbias, lane, R0, row0, N);

        // ---- k = Ah @ Wk^T ----
        #pragma unroll
        for (int i = 0; i < 16; i++)
            #pragma unroll
            for (int j = 0; j < 4; j++) acc[i][j] = 0.f;
        gemm_pass(acc, sb + AH_OFF, sb + WK_OFF, lane, R0);
        store_out(acc, g_k, sbias + 128, lane, R0, row0, N);

        // ---- v = Ah@Wvh + Al@Wvh + Ah@Wvl (3-pass split) ----
        #pragma unroll
        for (int i = 0; i < 16; i++)
            #pragma unroll
            for (int j = 0; j < 4; j++) acc[i][j] = 0.f;
        gemm_pass(acc, sb + AH_OFF, sb + WVH_OFF, lane, R0);
        gemm_pass(acc, sb + AL_OFF, sb + WVH_OFF, lane, R0);
        gemm_pass(acc, sb + AH_OFF, sb + WVL_OFF, lane, R0);
        store_out(acc, g_v, sbias + 256, lane, R0, row0, N);

        __syncthreads();
    }
}

// ---------------- attention (max-free softmax; scores provably tiny) + exp_map ----------------
__global__ void __launch_bounds__(256)
edge_kernel(const float* __restrict__ curv, float* __restrict__ out, int N) {
    int lane = threadIdx.x & 31;
    int node = blockIdx.x * 8 + (threadIdx.x >> 5);
    if (node >= N) return;

    float4 qr = ((const float4*)g_q)[node * 32 + lane];
    int e0 = g_off[node];
    int e1 = g_off[node + 1];
    const float scale = 0.08838834764831845f;  // 1/sqrt(128)

    float z = 0.f;
    float4 acc = make_float4(0.f, 0.f, 0.f, 0.f);

    int e = e0;
    for (; e + 2 <= e1; e += 2) {
        int s0 = __ldg(&g_esrc[e]);
        int s1 = __ldg(&g_esrc[e + 1]);
        float4 k0 = ((const float4*)g_k)[s0 * 32 + lane];
        float4 k1 = ((const float4*)g_k)[s1 * 32 + lane];
        float4 v0 = ((const float4*)g_v)[s0 * 32 + lane];
        float4 v1 = ((const float4*)g_v)[s1 * 32 + lane];
        float d0 = qr.x * k0.x + qr.y * k0.y + qr.z * k0.z + qr.w * k0.w;
        float d1 = qr.x * k1.x + qr.y * k1.y + qr.z * k1.z + qr.w * k1.w;
        #pragma unroll
        for (int o = 16; o; o >>= 1) {
            d0 += __shfl_xor_sync(0xffffffffu, d0, o);
            d1 += __shfl_xor_sync(0xffffffffu, d1, o);
        }
        float p0 = __expf(d0 * scale);
        float p1 = __expf(d1 * scale);
        z += p0 + p1;
        acc.x += p0 * v0.x + p1 * v1.x;
        acc.y += p0 * v0.y + p1 * v1.y;
        acc.z += p0 * v0.z + p1 * v1.z;
        acc.w += p0 * v0.w + p1 * v1.w;
    }
    if (e < e1) {
        int s0 = __ldg(&g_esrc[e]);
        float4 k0 = ((const float4*)g_k)[s0 * 32 + lane];
        float4 v0 = ((const float4*)g_v)[s0 * 32 + lane];
        float d0 = qr.x * k0.x + qr.y * k0.y + qr.z * k0.z + qr.w * k0.w;
        d0 = wredsum(d0);
        float p0 = __expf(d0 * scale);
        z += p0;
        acc.x += p0 * v0.x;
        acc.y += p0 * v0.y;
        acc.z += p0 * v0.z;
        acc.w += p0 * v0.w;
    }

    float inv = 1.0f / z;
    float4 h = make_float4(acc.x * inv, acc.y * inv, acc.z * inv, acc.w * inv);
    float n2 = wredsum(h.x * h.x + h.y * h.y + h.z * h.z + h.w * h.w);
    float nrm = sqrtf(n2);
    float sc = sqrtf(curv[0]);
    float f = (nrm > 1e-30f) ? tanhf(0.5f * sc * nrm) / (sc * nrm) : 0.5f;
    ((float4*)out)[node * 32 + lane] =
        make_float4(f * h.x, f * h.y, f * h.z, f * h.w);
}

// ---------------- launch ----------------
extern "C" void kernel_launch(void* const* d_in, const int* in_sizes, int n_in,
                              void* d_out, int out_size) {
    const float* emb  = (const float*)d_in[0];
    const float* Wq   = (const float*)d_in[1];
    const float* bq   = (const float*)d_in[2];
    const float* Wk   = (const float*)d_in[3];
    const float* bk   = (const float*)d_in[4];
    const float* Wv   = (const float*)d_in[5];
    const float* bv   = (const float*)d_in[6];
    const float* curv = (const float*)d_in[7];
    const int*   src  = (const int*)d_in[8];
    const int*   dst  = (const int*)d_in[9];

    int N = in_sizes[0] / D;
    int E = in_sizes[8];
    int L = in_sizes[1] / (D * D);

    cudaFuncSetAttribute(qkv_gemm_hmma,
                         cudaFuncAttributeMaxDynamicSharedMemorySize, GEMM_SMEM);

    void* gx_v = nullptr;
    cudaGetSymbolAddress(&gx_v, g_x);
    float* gx = (float*)gx_v;

    int nb = (N + 1023) >> 10;
    zero_cnt_kernel<<<(N + 255) / 256, 256>>>(N);
    hist_kernel<<<(E + 255) / 256, 256>>>(dst, E);
    scan_local<<<nb, 256>>>(N);
    scan_tops<<<1, 128>>>(nb);
    scan_add<<<(N + 255) / 256, 256>>>(N, E);
    scatter_kernel<<<(E + 255) / 256, 256>>>(src, dst, E);

    int numTiles = (N + 127) / 128;
    int nodeBlocks = (N + 7) / 8;

    for (int l = 0; l < L; l++) {
        const float* xin = (l == 0) ? emb : gx;
        float* xout = (l == L - 1) ? (float*)d_out : gx;
        qkv_gemm_hmma<<<148, 256, GEMM_SMEM>>>(xin,
                                               Wq + l * D * D, bq + l * D,
                                               Wk + l * D * D, bk + l * D,
                                               Wv + l * D * D, bv + l * D,
                                               curv, N, numTiles);
        edge_kernel<<<nodeBlocks, 256>>>(curv, xout, N);
    }
}

// round 5
// speedup vs baseline: 2.8152x; 1.0981x over previous
#include <cuda_runtime.h>
#include <cuda_bf16.h>
#include <cuda_fp16.h>
#include <math.h>
#include <stdint.h>

#define D 128
#define MAXN 100000
#define MAXE 1600000

// ---------------- device scratch ----------------
__device__ float  g_q[MAXN * D];
__device__ __half g_kh[MAXN * D];
__device__ __half g_vh[MAXN * D];
__device__ float  g_x[MAXN * D];
__device__ int    g_cnt[MAXN];
__device__ int    g_off[MAXN + 1];
__device__ int    g_cur[MAXN];
__device__ int    g_esrc[MAXE];
__device__ int    g_bsum[128];
__device__ int    g_btop[128];

// ---------------- helpers ----------------
__device__ __forceinline__ uint32_t smem_u32(const void* p) {
    uint32_t a;
    asm("{ .reg .u64 t; cvta.to.shared.u64 t, %1; cvt.u32.u64 %0, t; }"
        : "=r"(a) : "l"(p));
    return a;
}
__device__ __forceinline__ unsigned short bfh(float x) {
    return __bfloat16_as_ushort(__float2bfloat16_rn(x));
}
__device__ __forceinline__ float bff(float x) {
    return __bfloat162float(__float2bfloat16_rn(x));
}
__device__ __forceinline__ unsigned pk(float a, float b) {
    return (unsigned)bfh(a) | ((unsigned)bfh(b) << 16);
}
__device__ __forceinline__ float wredsum(float v) {
    #pragma unroll
    for (int o = 16; o; o >>= 1) v += __shfl_xor_sync(0xffffffffu, v, o);
    return v;
}
__device__ __forceinline__ float4 h4f(uint2 u) {
    float2 fa = __half22float2(*reinterpret_cast<__half2*>(&u.x));
    float2 fb = __half22float2(*reinterpret_cast<__half2*>(&u.y));
    return make_float4(fa.x, fa.y, fb.x, fb.y);
}
__device__ __forceinline__ void ldsm_x4(uint32_t* r, uint32_t addr) {
    asm volatile("ldmatrix.sync.aligned.m8n8.x4.shared.b16 {%0,%1,%2,%3}, [%4];"
                 : "=r"(r[0]), "=r"(r[1]), "=r"(r[2]), "=r"(r[3]) : "r"(addr));
}
__device__ __forceinline__ void mma16816(float* d, const uint32_t* a,
                                         uint32_t b0, uint32_t b1) {
    asm volatile(
        "mma.sync.aligned.m16n8k16.row.col.f32.bf16.bf16.f32 "
        "{%0,%1,%2,%3}, {%4,%5,%6,%7}, {%8,%9}, {%0,%1,%2,%3};"
        : "+f"(d[0]), "+f"(d[1]), "+f"(d[2]), "+f"(d[3])
        : "r"(a[0]), "r"(a[1]), "r"(a[2]), "r"(a[3]), "r"(b0), "r"(b1));
}

// ---------------- CSR build ----------------
__global__ void hist_kernel(const int* __restrict__ dst, int E) {
    int i = blockIdx.x * blockDim.x + threadIdx.x;
    if (i < E) atomicAdd(&g_cnt[dst[i]], 1);
}
__global__ void scan_local(int N) {
    __shared__ int sh[256];
    int b = blockIdx.x, t = threadIdx.x;
    int i0 = b * 1024 + t * 4;
    int c0 = (i0 + 0 < N) ? g_cnt[i0 + 0] : 0;
    int c1 = (i0 + 1 < N) ? g_cnt[i0 + 1] : 0;
    int c2 = (i0 + 2 < N) ? g_cnt[i0 + 2] : 0;
    int c3 = (i0 + 3 < N) ? g_cnt[i0 + 3] : 0;
    int s = c0 + c1 + c2 + c3;
    sh[t] = s;
    __syncthreads();
    for (int o = 1; o < 256; o <<= 1) {
        int v = (t >= o) ? sh[t - o] : 0;
        __syncthreads();
        sh[t] += v;
        __syncthreads();
    }
    int ex = sh[t] - s;
    if (i0 + 0 < N) g_off[i0 + 0] = ex; ex += c0;
    if (i0 + 1 < N) g_off[i0 + 1] = ex; ex += c1;
    if (i0 + 2 < N) g_off[i0 + 2] = ex; ex += c2;
    if (i0 + 3 < N) g_off[i0 + 3] = ex;
    if (t == 255) g_bsum[b] = sh[255];
}
__global__ void scan_tops(int nb) {
    __shared__ int sh[128];
    int t = threadIdx.x;
    int v = (t < nb) ? g_bsum[t] : 0;
    sh[t] = v;
    __syncthreads();
    for (int o = 1; o < 128; o <<= 1) {
        int u = (t >= o) ? sh[t - o] : 0;
        __syncthreads();
        sh[t] += u;
        __syncthreads();
    }
    g_btop[t] = sh[t] - v;
}
__global__ void scan_add(int N, int E) {
    int i = blockIdx.x * blockDim.x + threadIdx.x;
    if (i < N) {
        int o = g_off[i] + g_btop[i >> 10];
        g_off[i] = o;
        g_cur[i] = o;
    }
    if (i == 0) g_off[N] = E;
}
__global__ void scatter_kernel(const int* __restrict__ src,
                               const int* __restrict__ dst, int E) {
    int i = blockIdx.x * blockDim.x + threadIdx.x;
    if (i < E) {
        int p = atomicAdd(&g_cur[dst[i]], 1);
        g_esrc[p] = src[i];
    }
}

// ---------------- fused log_map + q/k/v GEMM (HMMA mma.sync bf16) ----------------
// SMEM panels: 128 rows x 256 bytes, chunk-XOR swizzle: chunk' = chunk ^ (row&7)
#define AH_OFF   0
#define AL_OFF   32768
#define WQ_OFF   65536
#define WK_OFF   98304
#define WVH_OFF  131072
#define WVL_OFF  163840
#define BIAS_OFF 196608
#define GEMM_SMEM 199680

__device__ __forceinline__ void gemm_pass(float (*acc)[4], uint32_t Ap,
                                          uint32_t Bp, int lane, int R0) {
    int arow = R0 + (lane & 15);
    int brl = lane & 15;
    int chi = lane >> 4;
    uint32_t abase = Ap + arow * 256;
    int asw = arow & 7;
    #pragma unroll
    for (int kk = 0; kk < 8; kk++) {
        int cidx = kk * 2 + chi;
        uint32_t a[4];
        ldsm_x4(a, abase + (uint32_t)((cidx ^ asw) << 4));
        #pragma unroll
        for (int nb2 = 0; nb2 < 8; nb2++) {
            int brow = nb2 * 16 + brl;
            uint32_t b[4];
            ldsm_x4(b, Bp + brow * 256 + (uint32_t)((cidx ^ (brow & 7)) << 4));
            mma16816(acc[nb2 * 2 + 0], a, b[0], b[2]);
            mma16816(acc[nb2 * 2 + 1], a, b[1], b[3]);
        }
    }
}

__device__ __forceinline__ void store_out_f(float (*acc)[4], float* out,
                                            const float* bias, int lane, int R0,
                                            int row0, int N) {
    int g = lane >> 2, t = lane & 3;
    int r0g = row0 + R0 + g;
    int r1g = r0g + 8;
    #pragma unroll
    for (int nb = 0; nb < 16; nb++) {
        int col = nb * 8 + 2 * t;
        float b0 = bias[col], b1 = bias[col + 1];
        if (r0g < N)
            *(float2*)(out + r0g * 128 + col) =
                make_float2(acc[nb][0] + b0, acc[nb][1] + b1);
        if (r1g < N)
            *(float2*)(out + r1g * 128 + col) =
                make_float2(acc[nb][2] + b0, acc[nb][3] + b1);
    }
}

__device__ __forceinline__ void store_out_h(float (*acc)[4], __half* out,
                                            const float* bias, int lane, int R0,
                                            int row0, int N) {
    int g = lane >> 2, t = lane & 3;
    int r0g = row0 + R0 + g;
    int r1g = r0g + 8;
    #pragma unroll
    for (int nb = 0; nb < 16; nb++) {
        int col = nb * 8 + 2 * t;
        float b0 = bias[col], b1 = bias[col + 1];
        if (r0g < N)
            *(__half2*)(out + r0g * 128 + col) =
                __floats2half2_rn(acc[nb][0] + b0, acc[nb][1] + b1);
        if (r1g < N)
            *(__half2*)(out + r1g * 128 + col) =
                __floats2half2_rn(acc[nb][2] + b0, acc[nb][3] + b1);
    }
}

__global__ void __launch_bounds__(256, 1)
qkv_gemm_hmma(const float* __restrict__ xin,
              const float* __restrict__ Wq, const float* __restrict__ bq,
              const float* __restrict__ Wk, const float* __restrict__ bk,
              const float* __restrict__ Wv, const float* __restrict__ bv,
              const float* __restrict__ curv, int N, int numTiles) {
    extern __shared__ char dsm[];
    char* SB = (char*)((((uintptr_t)dsm) + 1023) & ~(uintptr_t)1023);
    uint32_t sb = smem_u32(SB);
    float* sbias = (float*)(SB + BIAS_OFF);

    int tid = threadIdx.x;
    int lane = tid & 31;
    int wid = tid >> 5;

    // ---- weights -> SMEM (bf16 hi; lo only for Wv), swizzled ----
    for (int it = 0; it < 16; it++) {
        int c = wid * 16 + it;
        float4 wq = ((const float4*)Wq)[c * 32 + lane];
        float4 wk = ((const float4*)Wk)[c * 32 + lane];
        float4 wv = ((const float4*)Wv)[c * 32 + lane];
        uint32_t off = (uint32_t)(c * 256 + (((lane >> 1) ^ (c & 7)) << 4) +
                                  (lane & 1) * 8);
        *(uint2*)(SB + WQ_OFF + off) = make_uint2(pk(wq.x, wq.y), pk(wq.z, wq.w));
        *(uint2*)(SB + WK_OFF + off) = make_uint2(pk(wk.x, wk.y), pk(wk.z, wk.w));
        *(uint2*)(SB + WVH_OFF + off) = make_uint2(pk(wv.x, wv.y), pk(wv.z, wv.w));
        float lx = wv.x - bff(wv.x), ly = wv.y - bff(wv.y);
        float lz = wv.z - bff(wv.z), lw = wv.w - bff(wv.w);
        *(uint2*)(SB + WVL_OFF + off) = make_uint2(pk(lx, ly), pk(lz, lw));
    }
    if (tid < 128) {
        sbias[tid] = bq[tid];
        sbias[128 + tid] = bk[tid];
        sbias[256 + tid] = bv[tid];
    }
    __syncthreads();

    float sc = sqrtf(curv[0]);
    float inv_sc2 = 2.0f / sc;
    int R0 = wid * 16;

    for (int tile = blockIdx.x; tile < numTiles; tile += gridDim.x) {
        int row0 = tile * 128;
        // ---- A fill: log_map(x) -> bf16 hi/lo panels ----
        for (int it = 0; it < 16; it++) {
            int m = wid * 16 + it;
            int grow = row0 + m;
            float4 xv = (grow < N) ? ((const float4*)xin)[grow * 32 + lane]
                                   : make_float4(0.f, 0.f, 0.f, 0.f);
            float n2 = wredsum(xv.x * xv.x + xv.y * xv.y + xv.z * xv.z + xv.w * xv.w);
            float nrm = sqrtf(n2);
            float f = (nrm > 1e-30f) ? inv_sc2 * atanhf(sc * nrm) / nrm : 2.0f;
            float tx = f * xv.x, ty = f * xv.y, tz = f * xv.z, tw = f * xv.w;
            uint32_t off = (uint32_t)(m * 256 + (((lane >> 1) ^ (m & 7)) << 4) +
                                      (lane & 1) * 8);
            *(uint2*)(SB + AH_OFF + off) = make_uint2(pk(tx, ty), pk(tz, tw));
            float lx = tx - bff(tx), ly = ty - bff(ty);
            float lz = tz - bff(tz), lw = tw - bff(tw);
            *(uint2*)(SB + AL_OFF + off) = make_uint2(pk(lx, ly), pk(lz, lw));
        }
        __syncthreads();

        float acc[16][4];
        // ---- q = Ah @ Wq^T  (fp32 out) ----
        #pragma unroll
        for (int i = 0; i < 16; i++)
            #pragma unroll
            for (int j = 0; j < 4; j++) acc[i][j] = 0.f;
        gemm_pass(acc, sb + AH_OFF, sb + WQ_OFF, lane, R0);
        store_out_f(acc, g_q, sbias, lane, R0, row0, N);

        // ---- k = Ah @ Wk^T  (fp16 out) ----
        #pragma unroll
        for (int i = 0; i < 16; i++)
            #pragma unroll
            for (int j = 0; j < 4; j++) acc[i][j] = 0.f;
        gemm_pass(acc, sb + AH_OFF, sb + WK_OFF, lane, R0);
        store_out_h(acc, g_kh, sbias + 128, lane, R0, row0, N);

        // ---- v = Ah@Wvh + Al@Wvh + Ah@Wvl  (fp16 out) ----
        #pragma unroll
        for (int i = 0; i < 16; i++)
            #pragma unroll
            for (int j = 0; j < 4; j++) acc[i][j] = 0.f;
        gemm_pass(acc, sb + AH_OFF, sb + WVH_OFF, lane, R0);
        gemm_pass(acc, sb + AL_OFF, sb + WVH_OFF, lane, R0);
        gemm_pass(acc, sb + AH_OFF, sb + WVL_OFF, lane, R0);
        store_out_h(acc, g_vh, sbias + 256, lane, R0, row0, N);

        __syncthreads();
    }
}

// ---------------- attention (max-free softmax) + exp_map; fp16 gathers ----------------
__global__ void __launch_bounds__(256)
edge_kernel(const float* __restrict__ curv, float* __restrict__ out, int N) {
    int lane = threadIdx.x & 31;
    int node = blockIdx.x * 8 + (threadIdx.x >> 5);
    if (node >= N) return;

    float4 qr = ((const float4*)g_q)[node * 32 + lane];
    int e0 = g_off[node];
    int e1 = g_off[node + 1];
    const float scale = 0.08838834764831845f;  // 1/sqrt(128)
    const uint2* kp = (const uint2*)g_kh;
    const uint2* vp = (const uint2*)g_vh;

    float z = 0.f;
    float4 acc = make_float4(0.f, 0.f, 0.f, 0.f);

    int e = e0;
    for (; e + 4 <= e1; e += 4) {
        int s0 = __ldg(&g_esrc[e]);
        int s1 = __ldg(&g_esrc[e + 1]);
        int s2 = __ldg(&g_esrc[e + 2]);
        int s3 = __ldg(&g_esrc[e + 3]);
        uint2 ku0 = __ldg(&kp[s0 * 32 + lane]);
        uint2 ku1 = __ldg(&kp[s1 * 32 + lane]);
        uint2 ku2 = __ldg(&kp[s2 * 32 + lane]);
        uint2 ku3 = __ldg(&kp[s3 * 32 + lane]);
        uint2 vu0 = __ldg(&vp[s0 * 32 + lane]);
        uint2 vu1 = __ldg(&vp[s1 * 32 + lane]);
        uint2 vu2 = __ldg(&vp[s2 * 32 + lane]);
        uint2 vu3 = __ldg(&vp[s3 * 32 + lane]);
        float4 k0 = h4f(ku0), k1 = h4f(ku1), k2 = h4f(ku2), k3 = h4f(ku3);
        float d0 = qr.x * k0.x + qr.y * k0.y + qr.z * k0.z + qr.w * k0.w;
        float d1 = qr.x * k1.x + qr.y * k1.y + qr.z * k1.z + qr.w * k1.w;
        float d2 = qr.x * k2.x + qr.y * k2.y + qr.z * k2.z + qr.w * k2.w;
        float d3 = qr.x * k3.x + qr.y * k3.y + qr.z * k3.z + qr.w * k3.w;
        #pragma unroll
        for (int o = 16; o; o >>= 1) {
            d0 += __shfl_xor_sync(0xffffffffu, d0, o);
            d1 += __shfl_xor_sync(0xffffffffu, d1, o);
            d2 += __shfl_xor_sync(0xffffffffu, d2, o);
            d3 += __shfl_xor_sync(0xffffffffu, d3, o);
        }
        float p0 = __expf(d0 * scale);
        float p1 = __expf(d1 * scale);
        float p2 = __expf(d2 * scale);
        float p3 = __expf(d3 * scale);
        z += (p0 + p1) + (p2 + p3);
        float4 v0 = h4f(vu0), v1 = h4f(vu1), v2 = h4f(vu2), v3 = h4f(vu3);
        acc.x += p0 * v0.x + p1 * v1.x + p2 * v2.x + p3 * v3.x;
        acc.y += p0 * v0.y + p1 * v1.y + p2 * v2.y + p3 * v3.y;
        acc.z += p0 * v0.z + p1 * v1.z + p2 * v2.z + p3 * v3.z;
        acc.w += p0 * v0.w + p1 * v1.w + p2 * v2.w + p3 * v3.w;
    }
    for (; e < e1; e++) {
        int s0 = __ldg(&g_esrc[e]);
        float4 k0 = h4f(__ldg(&kp[s0 * 32 + lane]));
        float4 v0 = h4f(__ldg(&vp[s0 * 32 + lane]));
        float d0 = qr.x * k0.x + qr.y * k0.y + qr.z * k0.z + qr.w * k0.w;
        d0 = wredsum(d0);
        float p0 = __expf(d0 * scale);
        z += p0;
        acc.x += p0 * v0.x;
        acc.y += p0 * v0.y;
        acc.z += p0 * v0.z;
        acc.w += p0 * v0.w;
    }

    float inv = 1.0f / z;
    float4 h = make_float4(acc.x * inv, acc.y * inv, acc.z * inv, acc.w * inv);
    float n2 = wredsum(h.x * h.x + h.y * h.y + h.z * h.z + h.w * h.w);
    float nrm = sqrtf(n2);
    float sc = sqrtf(curv[0]);
    float f = (nrm > 1e-30f) ? tanhf(0.5f * sc * nrm) / (sc * nrm) : 0.5f;
    ((float4*)out)[node * 32 + lane] =
        make_float4(f * h.x, f * h.y, f * h.z, f * h.w);
}

// ---------------- launch ----------------
extern "C" void kernel_launch(void* const* d_in, const int* in_sizes, int n_in,
                              void* d_out, int out_size) {
    const float* emb  = (const float*)d_in[0];
    const float* Wq   = (const float*)d_in[1];
    const float* bq   = (const float*)d_in[2];
    const float* Wk   = (const float*)d_in[3];
    const float* bk   = (const float*)d_in[4];
    const float* Wv   = (const float*)d_in[5];
    const float* bv   = (const float*)d_in[6];
    const float* curv = (const float*)d_in[7];
    const int*   src  = (const int*)d_in[8];
    const int*   dst  = (const int*)d_in[9];

    int N = in_sizes[0] / D;
    int E = in_sizes[8];
    int L = in_sizes[1] / (D * D);

    cudaFuncSetAttribute(qkv_gemm_hmma,
                         cudaFuncAttributeMaxDynamicSharedMemorySize, GEMM_SMEM);

    void* gx_v = nullptr;
    cudaGetSymbolAddress(&gx_v, g_x);
    float* gx = (float*)gx_v;
    void* gcnt_v = nullptr;
    cudaGetSymbolAddress(&gcnt_v, g_cnt);

    int nb = (N + 1023) >> 10;
    cudaMemsetAsync(gcnt_v, 0, (size_t)N * sizeof(int));
    hist_kernel<<<(E + 255) / 256, 256>>>(dst, E);
    scan_local<<<nb, 256>>>(N);
    scan_tops<<<1, 128>>>(nb);
    scan_add<<<(N + 255) / 256, 256>>>(N, E);
    scatter_kernel<<<(E + 255) / 256, 256>>>(src, dst, E);

    int numTiles = (N + 127) / 128;
    int nodeBlocks = (N + 7) / 8;

    for (int l = 0; l < L; l++) {
        const float* xin = (l == 0) ? emb : gx;
        float* xout = (l == L - 1) ? (float*)d_out : gx;
        qkv_gemm_hmma<<<148, 256, GEMM_SMEM>>>(xin,
                                               Wq + l * D * D, bq + l * D,
                                               Wk + l * D * D, bk + l * D,
                                               Wv + l * D * D, bv + l * D,
                                               curv, N, numTiles);
        edge_kernel<<<nodeBlocks, 256>>>(curv, xout, N);
    }
}